// round 17
// baseline (speedup 1.0000x reference)
#include <cuda_runtime.h>
#include <cuda_fp16.h>
#include <math.h>

#define Bb 128
#define Ss 800
#define Hh 512
#define Ee 256
#define Vv 34
#define Tt 128
#define KVE (Bb * Ss * Hh)
#define K1d 1280
#define K2d 1024
// smem: W chunks [0, WB) | X staging / attn scratch [WB, DYNB)
#define WB 165888
#define XSTG 4608            // one X stage: 32 k x 72 (64 b + 8 pad) halves
#define NSTG 3               // pipeline depth per warpgroup
#define DYNB (WB + 4 * NSTG * XSTG)   // 221184

typedef unsigned int uint32;

// ---------------- persistent device buffers ----------------
__device__ __align__(16) __half g_kh[KVE];
__device__ __align__(16) __half g_vh[KVE];
__device__ __align__(16) __half g_W1h[2048 * K1d];         // [r=u*4+g][k] fp16
__device__ __align__(16) __half g_W2h[2048 * K2d];
__device__ __align__(16) __half g_X1h[(768 + 1024) * Bb];  // ctx | emb | h0 x2 slots
__device__ __align__(16) __half g_X2h[(512 + 1024) * Bb];  // h0 | h1 x2 slots
__device__ __align__(16) float g_c0[Hh * Bb];
__device__ __align__(16) float g_c1[Hh * Bb];
__device__ __align__(16) float g_h1t[Bb * Hh];             // h1 fp32 [b][h]
__device__ __align__(16) float g_tail[Hh * Bb];
__device__ __align__(16) float g_energy[Bb * Ss];          // normalized weights
__device__ int g_pairA[64], g_pairB[64], g_sorted[Bb];
__device__ int g_tok[Bb * Tt];
__device__ int g_len[Bb];
__device__ unsigned g_bar_count;
__device__ volatile unsigned g_bar_gen;

__device__ __forceinline__ float sigf(float x) { return 1.0f / (1.0f + expf(-x)); }

__device__ __forceinline__ void cp16(void* dst, const void* src) {
    unsigned d = (unsigned)__cvta_generic_to_shared(dst);
    asm volatile("cp.async.cg.shared.global [%0],[%1],16;\n" :: "r"(d), "l"(src));
}

// 32-byte key load, keep-in-L2 hint (sm_103a requires v4.b64 for evict hints)
__device__ __forceinline__ ulonglong4 ld_keep32(const void* p) {
    ulonglong4 v;
    asm volatile("ld.global.nc.L2::evict_last.v4.b64 {%0,%1,%2,%3},[%4];"
                 : "=l"(v.x), "=l"(v.y), "=l"(v.z), "=l"(v.w) : "l"(p));
    return v;
}

__device__ __forceinline__ void gridbar() {
    __syncthreads();
    if (threadIdx.x == 0) {
        __threadfence();
        unsigned gen = g_bar_gen;
        if (atomicAdd(&g_bar_count, 1u) == gridDim.x - 1) {
            g_bar_count = 0;
            __threadfence();
            g_bar_gen = gen + 1;
        } else {
            while (g_bar_gen == gen) { }
        }
    }
    __syncthreads();
}

// ---------------- single setup kernel ----------------
__global__ void k_setup(const void* dec, const void* lens,
                        const float* __restrict__ Wih1, const float* __restrict__ Whh1,
                        const float* __restrict__ Wih2, const float* __restrict__ Whh2,
                        const float* __restrict__ key, const float* __restrict__ value,
                        const float* __restrict__ emb) {
    int gtid = blockIdx.x * blockDim.x + threadIdx.x;
    int stride = gridDim.x * blockDim.x;
    int tid = threadIdx.x;

    const int* L = (const int*)lens;
    bool is64 = (L[1] == 0 && L[3] == 0 && L[5] == 0 && L[7] == 0);

    if (gtid == 0) { g_bar_count = 0; g_bar_gen = 0; }
    if (blockIdx.x == 0) {
        __shared__ int ll[Bb];
        if (tid < Bb) {
            int lv = is64 ? (int)((const long long*)lens)[tid] : L[tid];
            g_len[tid] = lv;
            ll[tid] = lv;
        }
        for (int i = tid; i < Bb * Tt; i += blockDim.x)
            g_tok[i] = is64 ? (int)((const long long*)dec)[i] : ((const int*)dec)[i];
        __syncthreads();
        if (tid < Bb) {
            int li = ll[tid], r = 0;
#pragma unroll 16
            for (int j = 0; j < Bb; j++) {
                int lj = ll[j];
                if (lj < li || (lj == li && j < tid)) r++;
            }
            g_sorted[r] = tid;
        }
        __syncthreads();
        if (tid < 64) {
            g_pairA[tid] = g_sorted[tid];
            g_pairB[tid] = g_sorted[127 - tid];
        }
    }

    for (int i = gtid; i < 2048 * K1d; i += stride) {
        int r = i / K1d, k = i - r * K1d;
        int u = r >> 2, g = r & 3;
        int j = g * Hh + u;
        float w = (k < 768) ? Wih1[j * 768 + k] : Whh1[j * 512 + (k - 768)];
        g_W1h[i] = __float2half_rn(w);
    }
    for (int i = gtid; i < 2048 * K2d; i += stride) {
        int r = i / K2d, k = i - r * K2d;
        int u = r >> 2, g = r & 3;
        int j = g * Hh + u;
        float w = (k < 512) ? Wih2[j * 512 + k] : Whh2[j * 512 + (k - 512)];
        g_W2h[i] = __float2half_rn(w);
    }

    const float4* k4 = (const float4*)key;
    const float4* v4 = (const float4*)value;
    uint2* kh2 = (uint2*)g_kh;
    uint2* vh2 = (uint2*)g_vh;
    for (int i = gtid; i < KVE / 4; i += stride) {
        float4 kf = k4[i];
        half2 lo = __floats2half2_rn(kf.x, kf.y), hi = __floats2half2_rn(kf.z, kf.w);
        uint2 st; st.x = *(unsigned*)&lo; st.y = *(unsigned*)&hi;
        kh2[i] = st;
        float4 vf = v4[i];
        half2 lo2 = __floats2half2_rn(vf.x, vf.y), hi2 = __floats2half2_rn(vf.z, vf.w);
        uint2 sv; sv.x = *(unsigned*)&lo2; sv.y = *(unsigned*)&hi2;
        vh2[i] = sv;
    }

    for (int i = gtid; i < 1024 * Bb; i += stride) g_X1h[768 * Bb + i] = __float2half(0.f);
    for (int i = gtid; i < 1536 * Bb; i += stride) g_X2h[i] = __float2half(0.f);
    for (int idx = gtid; idx < Hh * Bb; idx += stride) {
        g_c0[idx] = 0.0f; g_c1[idx] = 0.0f; g_h1t[idx] = 0.0f;
        int b = idx & 127, h = idx >> 7;
        g_X1h[idx] = __float2half_rn(key[(size_t)b * Ss * Hh + h]);
    }
    for (int idx = gtid; idx < Ee * Bb; idx += stride) {
        int b = idx & 127, e = idx >> 7;
        long long tok = is64 ? ((const long long*)dec)[b * Tt] : (long long)((const int*)dec)[b * Tt];
        g_X1h[(512 + e) * Bb + b] = __float2half_rn(emb[(int)tok * Ee + e]);
    }
    for (int idx = gtid; idx < Hh * Bb; idx += stride) {
        int h = idx & 511, b = idx >> 9;
        int len = is64 ? (int)((const long long*)lens)[b] : L[b];
        float acc = 0.0f;
        const float* vb = value + (size_t)b * Ss * Hh + h;
        for (int s = len; s < Ss; s++) acc += vb[(size_t)s * Hh];
        g_tail[h * Bb + b] = acc;
    }
}

// ---------------- persistent mega-kernel ----------------
// 128 blocks x 1024 threads. LSTM: block = 32 W-rows x 64 batches.
// SCORE: block = batch. VALUE: block pair = len-sorted batch pair, h-half split.
__global__ void __launch_bounds__(1024, 1) k_loop(
    const float* __restrict__ emb, const float* __restrict__ fcW,
    const float* __restrict__ fcb, const float* __restrict__ bias1,
    const float* __restrict__ bias2, float* __restrict__ out)
{
    extern __shared__ __align__(16) char dyn[];
    int tid = threadIdx.x;
    int blk = blockIdx.x;
    int rg = blk >> 1;
    int bh = blk & 1;
    int r0 = rg * 32;
    int bcol0 = bh * 64;

    // ---- preload W into smem (once) ----
    {
        __half* Wsm = (__half*)dyn;
        for (int i = tid; i < 36 * 32 * 8; i += 1024) {
            int chunk = i >> 8;
            int rem = i & 255;
            int row = rem >> 3, q = rem & 7;
            __half* dst = Wsm + chunk * 2304 + row * 72 + q * 8;
            const __half* src = (chunk < 20)
                ? g_W1h + (size_t)(r0 + row) * K1d + chunk * 64 + q * 8
                : g_W2h + (size_t)(r0 + row) * K2d + (chunk - 20) * 64 + q * 8;
            cp16(dst, src);
        }
        asm volatile("cp.async.commit_group;\ncp.async.wait_group 0;\n");
        __syncthreads();
    }

    // ---- lstm phase (unchanged from R16) ----
    auto lstm_phase = [&](int layer, int slot, const float* bias) {
        const __half* Xa = (layer == 1) ? g_X1h : g_X2h;
        const int split  = (layer == 1) ? 768 : 512;
        const int Kdim   = (layer == 1) ? K1d : K2d;
        const __half* Xb = Xa + (size_t)(split + slot * 512) * Bb;
        float* cst = (layer == 1) ? g_c0 : g_c1;
        const int chunkBase = (layer == 1) ? 0 : 20;

        int u0 = rg * 8;
        int wg = tid >> 8;
        int wt = tid & 255;
        int lane = wt & 31, w8 = wt >> 5;
        int rt = w8 >> 2;
        int ct = w8 & 3;
        int Kwg = Kdim >> 2;
        int wgK0 = wg * Kwg;
        int nst = Kwg >> 5;
        char* xb0 = dyn + WB + wg * NSTG * XSTG;

        float acc[2][4];
#pragma unroll
        for (int j = 0; j < 2; j++)
#pragma unroll
            for (int q = 0; q < 4; q++) acc[j][q] = 0.f;

        auto issue = [&](int st) {
            int k0 = wgK0 + st * 32;
            __half* sX = (__half*)(xb0 + (st % NSTG) * XSTG);
            const __half* xbase = ((k0 < split) ? (Xa + (size_t)k0 * Bb)
                                                : (Xb + (size_t)(k0 - split) * Bb)) + bcol0;
            int r = wt >> 3, q = wt & 7;
            cp16(sX + r * 72 + q * 8, xbase + r * Bb + q * 8);
            asm volatile("cp.async.commit_group;\n");
        };

        issue(0);
        issue(1);
        for (int st = 0; st < nst; st++) {
            if (st + 2 < nst) {
                issue(st + 2);
                asm volatile("cp.async.wait_group 2;\n");
            } else if (st + 1 < nst) {
                asm volatile("cp.async.wait_group 1;\n");
            } else {
                asm volatile("cp.async.wait_group 0;\n");
            }
            asm volatile("bar.sync %0, 256;" :: "r"(wg + 1) : "memory");

            int k0 = wgK0 + st * 32;
            __half* Wt = (__half*)dyn + (chunkBase + (k0 >> 6)) * 2304;
            __half* Xs = (__half*)(xb0 + (st % NSTG) * XSTG);
            unsigned aaddr = (unsigned)__cvta_generic_to_shared(
                Wt + (rt * 16 + (lane & 15)) * 72 + ((lane >> 4) * 8)) + (k0 & 32) * 2;
            unsigned bbase = (unsigned)__cvta_generic_to_shared(Xs + (lane & 15) * 72);

#pragma unroll
            for (int ki = 0; ki < 2; ki++) {
                int kc = ki * 16;
                uint32 ah[4];
                asm volatile("ldmatrix.sync.aligned.m8n8.x4.shared.b16 {%0,%1,%2,%3},[%4];"
                             : "=r"(ah[0]), "=r"(ah[1]), "=r"(ah[2]), "=r"(ah[3])
                             : "r"(aaddr + kc * 2));
#pragma unroll
                for (int j = 0; j < 2; j++) {
                    int n0 = ct * 16 + j * 8;
                    uint32 b0, b1;
                    asm volatile("ldmatrix.sync.aligned.m8n8.x2.trans.shared.b16 {%0,%1},[%2];"
                                 : "=r"(b0), "=r"(b1)
                                 : "r"(bbase + (kc * 72 + n0) * 2));
                    asm volatile("mma.sync.aligned.m16n8k16.row.col.f32.f16.f16.f32 "
                                 "{%0,%1,%2,%3},{%4,%5,%6,%7},{%8,%9},{%0,%1,%2,%3};"
                                 : "+f"(acc[j][0]), "+f"(acc[j][1]), "+f"(acc[j][2]), "+f"(acc[j][3])
                                 : "r"(ah[0]), "r"(ah[1]), "r"(ah[2]), "r"(ah[3]), "r"(b0), "r"(b1));
                }
            }
            asm volatile("bar.sync %0, 256;" :: "r"(wg + 1) : "memory");
        }

        __syncthreads();
        float* P = (float*)(dyn + WB);
#pragma unroll
        for (int j = 0; j < 2; j++) {
            int col = ct * 16 + j * 8 + (lane & 3) * 2;
            int row = rt * 16 + (lane >> 2);
            *(float2*)(P + wg * 2048 + row * 64 + col)       = make_float2(acc[j][0], acc[j][1]);
            *(float2*)(P + wg * 2048 + (row + 8) * 64 + col) = make_float2(acc[j][2], acc[j][3]);
        }
        __syncthreads();
        if (tid < 512) {
            int bl = tid & 63, ul = tid >> 6;
            int u = u0 + ul;
            int b = bcol0 + bl;
            float gv[4];
#pragma unroll
            for (int g = 0; g < 4; g++) {
                int r = (ul * 4 + g) * 64 + bl;
                gv[g] = P[r] + P[2048 + r] + P[4096 + r] + P[6144 + r] + bias[g * Hh + u];
            }
            float c = cst[u * Bb + b];
            float cn = sigf(gv[1]) * c + sigf(gv[0]) * tanhf(gv[2]);
            float h = sigf(gv[3]) * tanhf(cn);
            cst[u * Bb + b] = cn;
            __half hh2 = __float2half_rn(h);
            if (layer == 1) {
                g_X2h[u * Bb + b] = hh2;
                g_X1h[(768 + (slot ^ 1) * 512 + u) * Bb + b] = hh2;
            } else {
                g_X2h[(512 + (slot ^ 1) * 512 + u) * Bb + b] = hh2;
                g_h1t[b * Hh + u] = h;
            }
        }
        __syncthreads();
    };

    // ---- attn smem (aliases X staging region, 55296 B available) ----
    char* abase = dyn + WB;
    float* sh1  = (float*)abase;             // 2048 B
    half2* sh1h = (half2*)(abase + 2048);    // 512 B
    float* sc   = (float*)(abase + 2560);    // 3200 B
    float* red  = (float*)(abase + 5760);    // 128 B
    float* sb2  = (float*)(abase + 5888);    // 8 B
    float* sctx = (float*)(abase + 6144);    // 32 parts x 256 floats = 32768 B

    for (int t = 0; t < Tt; t++) {
        int slot = t & 1;
        lstm_phase(1, slot, bias1);
        gridbar();
        lstm_phase(2, slot, bias2);
        gridbar();

        // ============ SCORE phase: block = batch (fixed 800 rows, balanced) ====
        {
            int b = blk;
            int lane = tid & 31, warp = tid >> 5;

            if (tid < Hh) sh1[tid] = __ldcg(&g_h1t[b * Hh + tid]);
            __syncthreads();
            if (tid < Hh / 2) sh1h[tid] = __floats2half2_rn(sh1[2 * tid], sh1[2 * tid + 1]);
            __syncthreads();

            half2 h1r[8];
            {
                uint4 a0 = ((const uint4*)sh1h)[lane * 2];
                uint4 a1 = ((const uint4*)sh1h)[lane * 2 + 1];
                h1r[0] = *(const half2*)&a0.x; h1r[1] = *(const half2*)&a0.y;
                h1r[2] = *(const half2*)&a0.z; h1r[3] = *(const half2*)&a0.w;
                h1r[4] = *(const half2*)&a1.x; h1r[5] = *(const half2*)&a1.y;
                h1r[6] = *(const half2*)&a1.z; h1r[7] = *(const half2*)&a1.w;
            }

            const char* kbase = (const char*)(g_kh + (size_t)b * Ss * Hh);
            for (int s = warp; s < Ss; s += 32) {
                ulonglong4 kv = ld_keep32(kbase + (size_t)s * 1024 + lane * 32);
                const half2* kp = (const half2*)&kv;
                float a = 0.0f;
#pragma unroll
                for (int j = 0; j < 8; j++) {
                    float2 kf = __half22float2(kp[j]);
                    float2 hf = __half22float2(h1r[j]);
                    a += kf.x * hf.x + kf.y * hf.y;
                }
#pragma unroll
                for (int o = 16; o; o >>= 1) a += __shfl_xor_sync(0xffffffffu, a, o);
                if (lane == 0) sc[s] = a;
            }
            __syncthreads();

            float m = (tid < Ss) ? sc[tid] : -3.4e38f;
#pragma unroll
            for (int o = 16; o; o >>= 1) m = fmaxf(m, __shfl_xor_sync(0xffffffffu, m, o));
            if (lane == 0) red[warp] = m;
            __syncthreads();
            if (warp == 0) {
                float v = red[lane];
#pragma unroll
                for (int o = 16; o; o >>= 1) v = fmaxf(v, __shfl_xor_sync(0xffffffffu, v, o));
                if (lane == 0) sb2[0] = v;
            }
            __syncthreads();
            float mx = sb2[0];
            float e = 0.0f;
            if (tid < Ss) e = __expf(sc[tid] - mx);
            float su = e;
#pragma unroll
            for (int o = 16; o; o >>= 1) su += __shfl_xor_sync(0xffffffffu, su, o);
            __syncthreads();
            if (lane == 0) red[warp] = su;
            __syncthreads();
            if (warp == 0) {
                float v = red[lane];
#pragma unroll
                for (int o = 16; o; o >>= 1) v += __shfl_xor_sync(0xffffffffu, v, o);
                if (lane == 0) sb2[1] = v;
            }
            __syncthreads();
            float rinv = 1.0f / sb2[1];
            int len = g_len[b];

            // publish normalized energies (value blocks read via L2)
            if (tid < len) g_energy[b * Ss + tid] = e * rinv;

            // fc logits
            const float4* h14 = (const float4*)sh1;
            for (int v = warp; v < Vv; v += 32) {
                const float4* fw = (const float4*)(fcW + v * Hh);
                float a = 0.0f;
#pragma unroll
                for (int i = 0; i < 4; i++) {
                    float4 wv = fw[lane + 32 * i];
                    float4 hv = h14[lane + 32 * i];
                    a += wv.x * hv.x + wv.y * hv.y + wv.z * hv.z + wv.w * hv.w;
                }
#pragma unroll
                for (int o = 16; o; o >>= 1) a += __shfl_xor_sync(0xffffffffu, a, o);
                if (lane == 0) out[(size_t)b * (Tt * Vv) + t * Vv + v] = a + fcb[v];
            }

            // prefill embedding for next step
            if (t < Tt - 1 && tid < Ee) {
                int tok = g_tok[b * Tt + (t + 1)];
                g_X1h[(512 + tid) * Bb + b] = __float2half_rn(emb[tok * Ee + tid]);
            }
        }
        gridbar();

        // ============ VALUE phase: len-sorted pair, h-half split, no combine ===
        {
            int pair = blk >> 1, hhalf = blk & 1;
            int hbase = hhalf * 256;
            int lane = tid & 31, part = tid >> 5;   // 32 parts x 32 lanes

#pragma unroll 1
            for (int which = 0; which < 2; which++) {
                int b = which ? g_pairB[pair] : g_pairA[pair];
                int len = g_len[b];
                const char* vbase = (const char*)(g_vh + (size_t)b * Ss * Hh) + hbase * 2;
                const float* eb = g_energy + b * Ss;

                float accf[8];
#pragma unroll
                for (int i = 0; i < 8; i++) accf[i] = 0.0f;
#pragma unroll 2
                for (int s = part; s < len; s += 32) {
                    float ee = __ldcg(eb + s);
                    uint4 v = __ldcg((const uint4*)(vbase + (size_t)s * 1024 + lane * 16));
                    const half2* vp = (const half2*)&v;
#pragma unroll
                    for (int j = 0; j < 4; j++) {
                        float2 vf = __half22float2(vp[j]);
                        accf[2 * j]     += ee * vf.x;
                        accf[2 * j + 1] += ee * vf.y;
                    }
                }
                float4* dst = (float4*)(sctx + part * 256 + lane * 8);
                dst[0] = make_float4(accf[0], accf[1], accf[2], accf[3]);
                dst[1] = make_float4(accf[4], accf[5], accf[6], accf[7]);
                __syncthreads();
                if (tid < 256) {
                    float v = 0.0f;
#pragma unroll
                    for (int p = 0; p < 32; p++) v += sctx[p * 256 + tid];
                    int h = hbase + tid;
                    float ctx = v + 1e-9f * g_tail[h * Bb + b];
                    g_X1h[h * Bb + b] = __float2half_rn(ctx);
                }
                __syncthreads();
            }
        }
        gridbar();
    }
}

// ---------------- host ----------------
extern "C" void kernel_launch(void* const* d_in, const int* in_sizes, int n_in,
                              void* d_out, int out_size) {
    const float* key   = (const float*)d_in[0];
    const float* value = (const float*)d_in[1];
    const void*  dec   = d_in[2];
    const void*  lens  = d_in[3];
    const float* emb   = (const float*)d_in[4];
    const float* Wih1  = (const float*)d_in[5];
    const float* Whh1  = (const float*)d_in[6];
    const float* b1    = (const float*)d_in[7];
    const float* Wih2  = (const float*)d_in[8];
    const float* Whh2  = (const float*)d_in[9];
    const float* b2    = (const float*)d_in[10];
    const float* fcW   = (const float*)d_in[11];
    const float* fcb   = (const float*)d_in[12];
    float* out = (float*)d_out;

    static bool attrSet = false;
    if (!attrSet) {
        cudaFuncSetAttribute(k_loop, cudaFuncAttributeMaxDynamicSharedMemorySize, DYNB);
        attrSet = true;
    }

    k_setup<<<2048, 256>>>(dec, lens, Wih1, Whh1, Wih2, Whh2, key, value, emb);
    k_loop<<<Bb, 1024, DYNB>>>(emb, fcW, fcb, b1, b2, out);
}